// round 3
// baseline (speedup 1.0000x reference)
#include <cuda_runtime.h>
#include <cuda_bf16.h>
#include <cstdint>

#define N_NODES 50000
#define E_EDGES 800000
#define F_IN    128
#define HID     256

// ---------------- scratch (static __device__, no allocation) ----------------
__device__ float g_agg[(size_t)N_NODES * HID];   // reused for agg1/agg2/agg3
__device__ float g_h1 [(size_t)N_NODES * HID];
__device__ float g_h2 [(size_t)N_NODES * HID];
__device__ int   g_deg[N_NODES];
__device__ int   g_rowptr[N_NODES + 1];
__device__ int   g_cursor[N_NODES];
__device__ int   g_csrsrc[E_EDGES];
__device__ int   g_is64;

// ---------------- helpers ----------------
__device__ __forceinline__ unsigned long long dup_f32(float v) {
    unsigned long long d;
    asm("mov.b64 %0, {%1,%1};" : "=l"(d) : "f"(v));
    return d;
}
__device__ __forceinline__ void unpack_f32x2(unsigned long long v, float& lo, float& hi) {
    asm("mov.b64 {%0,%1}, %2;" : "=f"(lo), "=f"(hi) : "l"(v));
}
__device__ __forceinline__ void fma2(unsigned long long& d,
                                     unsigned long long a, unsigned long long b) {
    asm("fma.rn.f32x2 %0, %1, %2, %0;" : "+l"(d) : "l"(a), "l"(b));
}

__device__ __forceinline__ long long load_edge(const void* ei, int idx) {
    if (g_is64) return ((const long long*)ei)[idx];
    return (long long)((const int*)ei)[idx];
}

// ---------------- dtype detection for edge_index ----------------
__global__ void detect_kernel(const void* ei) {
    if (threadIdx.x == 0 && blockIdx.x == 0) {
        const long long* p = (const long long*)ei;
        int ok = 1;
        for (int i = 0; i < 128; i++) {
            long long v = p[i];
            if (v < 0 || v >= N_NODES) { ok = 0; break; }
        }
        g_is64 = ok;
    }
}

// ---------------- CSR build ----------------
__global__ void zero_deg_kernel() {
    int i = blockIdx.x * blockDim.x + threadIdx.x;
    if (i < N_NODES) g_deg[i] = 0;
}

__global__ void hist_kernel(const void* ei) {
    int e = blockIdx.x * blockDim.x + threadIdx.x;
    if (e < E_EDGES) {
        int d = (int)load_edge(ei, E_EDGES + e);
        atomicAdd(&g_deg[d], 1);
    }
}

__global__ void scan_kernel() {
    __shared__ int warp_off[32];
    __shared__ int s_carry;
    int tid = threadIdx.x;                  // 1024 threads
    if (tid == 0) s_carry = 0;
    __syncthreads();
    for (int base = 0; base < N_NODES; base += 1024) {
        int i = base + tid;
        int v = (i < N_NODES) ? g_deg[i] : 0;
        int incl = v;
        #pragma unroll
        for (int off = 1; off < 32; off <<= 1) {
            int t = __shfl_up_sync(0xffffffffu, incl, off);
            if ((tid & 31) >= off) incl += t;
        }
        if ((tid & 31) == 31) warp_off[tid >> 5] = incl;
        __syncthreads();
        if (tid < 32) {
            int ws = warp_off[tid];
            int wincl = ws;
            #pragma unroll
            for (int off = 1; off < 32; off <<= 1) {
                int t = __shfl_up_sync(0xffffffffu, wincl, off);
                if (tid >= off) wincl += t;
            }
            warp_off[tid] = wincl - ws;     // exclusive offset of warp
        }
        __syncthreads();
        int excl = s_carry + warp_off[tid >> 5] + incl - v;
        if (i < N_NODES) { g_rowptr[i] = excl; g_cursor[i] = excl; }
        __syncthreads();
        if (tid == 1023) s_carry += warp_off[31] + incl;
        __syncthreads();
    }
    if (tid == 0) g_rowptr[N_NODES] = s_carry;
}

__global__ void scatter_kernel(const void* ei) {
    int e = blockIdx.x * blockDim.x + threadIdx.x;
    if (e < E_EDGES) {
        int s = (int)load_edge(ei, e);
        int d = (int)load_edge(ei, E_EDGES + e);
        int p = atomicAdd(&g_cursor[d], 1);
        g_csrsrc[p] = s;
    }
}

// ---------------- segment max (one block per node, one thread per feature) --
template<int F>
__global__ void segmax_kernel(const float* __restrict__ in, float* __restrict__ out) {
    int node = blockIdx.x;
    int s = g_rowptr[node];
    int t = g_rowptr[node + 1];
    int tid = threadIdx.x;
    float m = -3.402823466e+38f;
    int j = s;
    for (; j + 4 <= t; j += 4) {           // MLP=4 independent gathers
        int u0 = g_csrsrc[j + 0];
        int u1 = g_csrsrc[j + 1];
        int u2 = g_csrsrc[j + 2];
        int u3 = g_csrsrc[j + 3];
        float v0 = in[(size_t)u0 * F + tid];
        float v1 = in[(size_t)u1 * F + tid];
        float v2 = in[(size_t)u2 * F + tid];
        float v3 = in[(size_t)u3 * F + tid];
        m = fmaxf(m, fmaxf(fmaxf(v0, v1), fmaxf(v2, v3)));
    }
    for (; j < t; j++) {
        int u = g_csrsrc[j];
        m = fmaxf(m, in[(size_t)u * F + tid]);
    }
    out[(size_t)node * F + tid] = (t > s) ? m : 0.0f;   // isolated -> 0
}

// ---------------- fused SAGE GEMM: out = relu(Aagg@Bl + Ax@Br + bias) -------
// Tile: BM=64 rows x BN=256 cols (full H), BK=16, 256 threads (16x16),
// per-thread micro-tile 4 rows x 16 cols as 8 f32x2 accumulators per row.
// head mode: feat_out==nullptr, computes head_out[row] = relu_feat . whead + bhead
#define BM 64
#define BN 256
#define BK 16

__global__ __launch_bounds__(256)
void sage_gemm_kernel(const float* __restrict__ Aagg, const float* __restrict__ Ax,
                      const float* __restrict__ Bl,   const float* __restrict__ Br,
                      const float* __restrict__ bias, int K,
                      float* __restrict__ feat_out,
                      const float* __restrict__ whead,
                      const float* __restrict__ bhead,
                      float* __restrict__ head_out) {
    __shared__ __align__(16) unsigned long long As2[BK][BM];  // dup-packed A, 8KB
    __shared__ __align__(16) float Bs[BK][BN];                // 16KB

    int tid = threadIdx.x;
    int tx = tid & 15, ty = tid >> 4;
    int bm0 = blockIdx.x * BM;

    unsigned long long acc[4][8];
    #pragma unroll
    for (int i = 0; i < 4; i++)
        #pragma unroll
        for (int j = 0; j < 8; j++) acc[i][j] = 0ULL;

    int am = tid >> 2;            // 0..63  (row in A tile)
    int ak = (tid & 3) * 4;       // 0,4,8,12 (k offset in A tile)
    int bk = tid >> 4;            // 0..15  (k row in B tile)
    int bc = (tid & 15) * 4;      // 0..60  (col base in B tile)

    for (int pass = 0; pass < 2; ++pass) {
        const float* A = pass ? Ax : Aagg;
        const float* B = pass ? Br : Bl;
        for (int kt = 0; kt < K; kt += BK) {
            // load A tile (64x16), dup-pack into As2[k][m]
            float4 av = make_float4(0.f, 0.f, 0.f, 0.f);
            int row = bm0 + am;
            if (row < N_NODES)
                av = *(const float4*)&A[(size_t)row * K + kt + ak];
            As2[ak + 0][am] = dup_f32(av.x);
            As2[ak + 1][am] = dup_f32(av.y);
            As2[ak + 2][am] = dup_f32(av.z);
            As2[ak + 3][am] = dup_f32(av.w);
            // load B tile (16x256)
            #pragma unroll
            for (int q = 0; q < 4; q++)
                *(float4*)&Bs[bk][bc + q * 64] =
                    *(const float4*)&B[(size_t)(kt + bk) * 256 + bc + q * 64];
            __syncthreads();

            #pragma unroll
            for (int kk = 0; kk < BK; kk++) {
                const ulonglong2* bp = (const ulonglong2*)&Bs[kk][tx * 16];
                ulonglong2 t0 = bp[0], t1 = bp[1], t2 = bp[2], t3 = bp[3];
                unsigned long long b[8] = {t0.x, t0.y, t1.x, t1.y,
                                           t2.x, t2.y, t3.x, t3.y};
                const ulonglong2* ap = (const ulonglong2*)&As2[kk][ty * 4];
                ulonglong2 a01 = ap[0], a23 = ap[1];
                unsigned long long a[4] = {a01.x, a01.y, a23.x, a23.y};
                #pragma unroll
                for (int i = 0; i < 4; i++)
                    #pragma unroll
                    for (int j = 0; j < 8; j++)
                        fma2(acc[i][j], a[i], b[j]);
            }
            __syncthreads();
        }
    }

    if (whead == nullptr) {
        // feature epilogue: bias + relu, store 4x16 per thread
        #pragma unroll
        for (int i = 0; i < 4; i++) {
            int row = bm0 + ty * 4 + i;
            if (row >= N_NODES) continue;
            #pragma unroll
            for (int q = 0; q < 4; q++) {
                float x0, x1, x2, x3;
                unpack_f32x2(acc[i][2 * q + 0], x0, x1);
                unpack_f32x2(acc[i][2 * q + 1], x2, x3);
                int c = tx * 16 + q * 4;
                float4 o;
                o.x = fmaxf(x0 + bias[c + 0], 0.f);
                o.y = fmaxf(x1 + bias[c + 1], 0.f);
                o.z = fmaxf(x2 + bias[c + 2], 0.f);
                o.w = fmaxf(x3 + bias[c + 3], 0.f);
                *(float4*)&feat_out[(size_t)row * 256 + c] = o;
            }
        }
    } else {
        // head epilogue: relu then dot with whead, reduce across 16 tx lanes
        #pragma unroll
        for (int i = 0; i < 4; i++) {
            float s = 0.f;
            #pragma unroll
            for (int j = 0; j < 8; j++) {
                float x0, x1;
                unpack_f32x2(acc[i][j], x0, x1);
                int c = tx * 16 + j * 2;
                s += fmaxf(x0 + bias[c + 0], 0.f) * whead[c + 0];
                s += fmaxf(x1 + bias[c + 1], 0.f) * whead[c + 1];
            }
            #pragma unroll
            for (int off = 8; off; off >>= 1)
                s += __shfl_xor_sync(0xffffffffu, s, off);
            int row = bm0 + ty * 4 + i;
            if (tx == 0 && row < N_NODES) head_out[row] = s + bhead[0];
        }
    }
}

// ---------------- launcher ----------------
extern "C" void kernel_launch(void* const* d_in, const int* in_sizes, int n_in,
                              void* d_out, int out_size) {
    const float* x   = (const float*)d_in[0];
    const void*  ei  = d_in[1];
    const float *Wl1 = (const float*)d_in[2],  *bl1 = (const float*)d_in[3],
                *Wr1 = (const float*)d_in[4];
    const float *Wl2 = (const float*)d_in[5],  *bl2 = (const float*)d_in[6],
                *Wr2 = (const float*)d_in[7];
    const float *Wla = (const float*)d_in[8],  *bla = (const float*)d_in[9],
                *Wra = (const float*)d_in[10], *Wa  = (const float*)d_in[11],
                *ba  = (const float*)d_in[12];
    const float *Wlm = (const float*)d_in[13], *blm = (const float*)d_in[14],
                *Wrm = (const float*)d_in[15], *Wm  = (const float*)d_in[16],
                *bm  = (const float*)d_in[17];
    float* out = (float*)d_out;

    float *agg, *h1, *h2;
    cudaGetSymbolAddress((void**)&agg, g_agg);
    cudaGetSymbolAddress((void**)&h1,  g_h1);
    cudaGetSymbolAddress((void**)&h2,  g_h2);

    const int GEMM_GRID = (N_NODES + BM - 1) / BM;   // 782

    detect_kernel<<<1, 32>>>(ei);
    zero_deg_kernel<<<(N_NODES + 1023) / 1024, 1024>>>();
    hist_kernel<<<(E_EDGES + 511) / 512, 512>>>(ei);
    scan_kernel<<<1, 1024>>>();
    scatter_kernel<<<(E_EDGES + 511) / 512, 512>>>(ei);

    // layer 1
    segmax_kernel<F_IN><<<N_NODES, F_IN>>>(x, agg);
    sage_gemm_kernel<<<GEMM_GRID, 256>>>(agg, x, Wl1, Wr1, bl1, F_IN,
                                         h1, nullptr, nullptr, nullptr);
    // layer 2
    segmax_kernel<HID><<<N_NODES, HID>>>(h1, agg);
    sage_gemm_kernel<<<GEMM_GRID, 256>>>(agg, h1, Wl2, Wr2, bl2, HID,
                                         h2, nullptr, nullptr, nullptr);
    // layer 3 aggregation shared by both heads
    segmax_kernel<HID><<<N_NODES, HID>>>(h2, agg);
    sage_gemm_kernel<<<GEMM_GRID, 256>>>(agg, h2, Wla, Wra, bla, HID,
                                         nullptr, Wa, ba, out);
    sage_gemm_kernel<<<GEMM_GRID, 256>>>(agg, h2, Wlm, Wrm, blm, HID,
                                         nullptr, Wm, bm, out + N_NODES);
}

// round 4
// speedup vs baseline: 2.7078x; 2.7078x over previous
#include <cuda_runtime.h>
#include <cuda_bf16.h>
#include <cstdint>

#define N_NODES 50000
#define E_EDGES 800000
#define F_IN    128
#define HID     256

#define SCAN_BLOCKS 49   // ceil(50000/1024)

// ---------------- scratch (static __device__, no allocation) ----------------
__device__ float g_agg[(size_t)N_NODES * HID];
__device__ float g_h1 [(size_t)N_NODES * HID];
__device__ float g_h2 [(size_t)N_NODES * HID];
__device__ int   g_deg[N_NODES];
__device__ int   g_rowptr[N_NODES + 1];
__device__ int   g_cursor[N_NODES];
__device__ int   g_csrsrc[E_EDGES];
__device__ int   g_is64;
__device__ int   g_flag[SCAN_BLOCKS + 1];
__device__ int   g_pref[SCAN_BLOCKS + 1];

// ---------------- helpers ----------------
__device__ __forceinline__ unsigned long long dup_f32(float v) {
    unsigned long long d;
    asm("mov.b64 %0, {%1,%1};" : "=l"(d) : "f"(v));
    return d;
}
__device__ __forceinline__ void unpack_f32x2(unsigned long long v, float& lo, float& hi) {
    asm("mov.b64 {%0,%1}, %2;" : "=f"(lo), "=f"(hi) : "l"(v));
}
__device__ __forceinline__ void fma2(unsigned long long& d,
                                     unsigned long long a, unsigned long long b) {
    asm("fma.rn.f32x2 %0, %1, %2, %0;" : "+l"(d) : "l"(a), "l"(b));
}
__device__ __forceinline__ long long load_edge(const void* ei, int idx) {
    if (g_is64) return ((const long long*)ei)[idx];
    return (long long)((const int*)ei)[idx];
}

// ---------------- init: zero deg + flags, detect edge dtype ----------------
__global__ void init_kernel(const void* ei) {
    int i = blockIdx.x * blockDim.x + threadIdx.x;
    if (i < N_NODES) g_deg[i] = 0;
    if (i <= SCAN_BLOCKS) { g_flag[i] = 0; g_pref[i] = 0; }
    if (i == 0) {
        const long long* p = (const long long*)ei;
        int ok = 1;
        for (int k = 0; k < 128; k++) {
            long long v = p[k];
            if (v < 0 || v >= N_NODES) { ok = 0; break; }
        }
        g_is64 = ok;
    }
}

__global__ void hist_kernel(const void* ei) {
    int e = blockIdx.x * blockDim.x + threadIdx.x;
    if (e < E_EDGES) {
        int d = (int)load_edge(ei, E_EDGES + e);
        atomicAdd(&g_deg[d], 1);
    }
}

// ---------------- chained multi-block exclusive scan (49 blocks x 1024) -----
__global__ __launch_bounds__(1024)
void scan_kernel() {
    __shared__ int wsum[32];
    __shared__ int s_pref;
    int tid = threadIdx.x, b = blockIdx.x;
    int wid = tid >> 5, lane = tid & 31;
    int i = b * 1024 + tid;
    int v = (i < N_NODES) ? g_deg[i] : 0;

    int incl = v;
    #pragma unroll
    for (int off = 1; off < 32; off <<= 1) {
        int t = __shfl_up_sync(0xffffffffu, incl, off);
        if (lane >= off) incl += t;
    }
    if (lane == 31) wsum[wid] = incl;
    __syncthreads();
    if (tid < 32) {
        int x = wsum[tid];
        #pragma unroll
        for (int off = 1; off < 32; off <<= 1) {
            int t = __shfl_up_sync(0xffffffffu, x, off);
            if (tid >= off) x += t;
        }
        wsum[tid] = x;           // inclusive over warp sums
    }
    __syncthreads();
    int excl = (wid ? wsum[wid - 1] : 0) + incl - v;

    if (tid == 0) {
        int total = wsum[31];
        int p = 0;
        if (b > 0) {
            while (atomicAdd(&g_flag[b - 1], 0) == 0) { }
            p = *((volatile int*)&g_pref[b - 1]);
        }
        *((volatile int*)&g_pref[b]) = p + total;
        __threadfence();
        atomicExch(&g_flag[b], 1);
        s_pref = p;
    }
    __syncthreads();
    if (i < N_NODES) {
        int r = s_pref + excl;
        g_rowptr[i] = r;
        g_cursor[i] = r;
    }
    if (b == 0 && tid == 0) g_rowptr[N_NODES] = E_EDGES;
}

__global__ void scatter_kernel(const void* ei) {
    int e = blockIdx.x * blockDim.x + threadIdx.x;
    if (e < E_EDGES) {
        int s = (int)load_edge(ei, e);
        int d = (int)load_edge(ei, E_EDGES + e);
        int p = atomicAdd(&g_cursor[d], 1);
        g_csrsrc[p] = s;
    }
}

// ---------------- segment max, float4 vectorized ----------------------------
// tpn = F/4 threads per node; 256-thread blocks handle 256/tpn nodes each.
template<int F>
__global__ __launch_bounds__(256)
void segmax_kernel(const float4* __restrict__ in, float4* __restrict__ out) {
    const int TPN = F / 4;
    const int NPB = 256 / TPN;
    int node = blockIdx.x * NPB + threadIdx.x / TPN;
    int lane = threadIdx.x % TPN;
    if (node >= N_NODES) return;
    int s = g_rowptr[node];
    int t = g_rowptr[node + 1];
    const float NEG = -3.402823466e+38f;
    float4 m = make_float4(NEG, NEG, NEG, NEG);
    int j = s;
    for (; j + 4 <= t; j += 4) {
        int u0 = g_csrsrc[j + 0];
        int u1 = g_csrsrc[j + 1];
        int u2 = g_csrsrc[j + 2];
        int u3 = g_csrsrc[j + 3];
        float4 v0 = in[(size_t)u0 * TPN + lane];
        float4 v1 = in[(size_t)u1 * TPN + lane];
        float4 v2 = in[(size_t)u2 * TPN + lane];
        float4 v3 = in[(size_t)u3 * TPN + lane];
        m.x = fmaxf(m.x, fmaxf(fmaxf(v0.x, v1.x), fmaxf(v2.x, v3.x)));
        m.y = fmaxf(m.y, fmaxf(fmaxf(v0.y, v1.y), fmaxf(v2.y, v3.y)));
        m.z = fmaxf(m.z, fmaxf(fmaxf(v0.z, v1.z), fmaxf(v2.z, v3.z)));
        m.w = fmaxf(m.w, fmaxf(fmaxf(v0.w, v1.w), fmaxf(v2.w, v3.w)));
    }
    for (; j < t; j++) {
        int u = g_csrsrc[j];
        float4 v = in[(size_t)u * TPN + lane];
        m.x = fmaxf(m.x, v.x); m.y = fmaxf(m.y, v.y);
        m.z = fmaxf(m.z, v.z); m.w = fmaxf(m.w, v.w);
    }
    if (t <= s) m = make_float4(0.f, 0.f, 0.f, 0.f);
    out[(size_t)node * TPN + lane] = m;
}

// ---------------- fused SAGE GEMM: out = relu(Aagg@Bl + Ax@Br + bias) -------
// BM=64 x BN=256 (full H), BK=16, 256 threads (16x16).
// Per-thread columns: tx*4 + q*64 (q=0..3) -> conflict-free LDS.128 on Bs.
// head mode: feat_out==nullptr; head_out[row] = relu_feat . whead + bhead.
#define BM 64
#define BN 256
#define BK 16

__global__ __launch_bounds__(256)
void sage_gemm_kernel(const float* __restrict__ Aagg, const float* __restrict__ Ax,
                      const float* __restrict__ Bl,   const float* __restrict__ Br,
                      const float* __restrict__ bias, int K,
                      float* __restrict__ feat_out,
                      const float* __restrict__ whead,
                      const float* __restrict__ bhead,
                      float* __restrict__ head_out) {
    __shared__ __align__(16) unsigned long long As2[BK][BM];  // dup-packed A
    __shared__ __align__(16) float Bs[BK][BN];

    int tid = threadIdx.x;
    int tx = tid & 15, ty = tid >> 4;
    int bm0 = blockIdx.x * BM;

    unsigned long long acc[4][8];
    #pragma unroll
    for (int i = 0; i < 4; i++)
        #pragma unroll
        for (int j = 0; j < 8; j++) acc[i][j] = 0ULL;

    int am = tid >> 2;            // 0..63 row in A tile
    int ak = (tid & 3) * 4;       // k offset in A tile
    int bk = tid >> 4;            // 0..15 k row in B tile
    int bc = (tid & 15) * 4;      // col base in B tile

    for (int pass = 0; pass < 2; ++pass) {
        const float* A = pass ? Ax : Aagg;
        const float* B = pass ? Br : Bl;
        for (int kt = 0; kt < K; kt += BK) {
            float4 av = make_float4(0.f, 0.f, 0.f, 0.f);
            int row = bm0 + am;
            if (row < N_NODES)
                av = *(const float4*)&A[(size_t)row * K + kt + ak];
            As2[ak + 0][am] = dup_f32(av.x);
            As2[ak + 1][am] = dup_f32(av.y);
            As2[ak + 2][am] = dup_f32(av.z);
            As2[ak + 3][am] = dup_f32(av.w);
            #pragma unroll
            for (int q = 0; q < 4; q++)
                *(float4*)&Bs[bk][bc + q * 64] =
                    *(const float4*)&B[(size_t)(kt + bk) * 256 + bc + q * 64];
            __syncthreads();

            #pragma unroll
            for (int kk = 0; kk < BK; kk++) {
                unsigned long long b[8];
                #pragma unroll
                for (int q = 0; q < 4; q++) {
                    ulonglong2 t = *(const ulonglong2*)&Bs[kk][tx * 4 + q * 64];
                    b[2 * q + 0] = t.x;
                    b[2 * q + 1] = t.y;
                }
                const ulonglong2* ap = (const ulonglong2*)&As2[kk][ty * 4];
                ulonglong2 a01 = ap[0], a23 = ap[1];
                unsigned long long a[4] = {a01.x, a01.y, a23.x, a23.y};
                #pragma unroll
                for (int i = 0; i < 4; i++)
                    #pragma unroll
                    for (int j = 0; j < 8; j++)
                        fma2(acc[i][j], a[i], b[j]);
            }
            __syncthreads();
        }
    }

    if (whead == nullptr) {
        #pragma unroll
        for (int i = 0; i < 4; i++) {
            int row = bm0 + ty * 4 + i;
            if (row >= N_NODES) continue;
            #pragma unroll
            for (int q = 0; q < 4; q++) {
                int c = tx * 4 + q * 64;
                float x0, x1, x2, x3;
                unpack_f32x2(acc[i][2 * q + 0], x0, x1);
                unpack_f32x2(acc[i][2 * q + 1], x2, x3);
                float4 o;
                o.x = fmaxf(x0 + bias[c + 0], 0.f);
                o.y = fmaxf(x1 + bias[c + 1], 0.f);
                o.z = fmaxf(x2 + bias[c + 2], 0.f);
                o.w = fmaxf(x3 + bias[c + 3], 0.f);
                *(float4*)&feat_out[(size_t)row * 256 + c] = o;
            }
        }
    } else {
        #pragma unroll
        for (int i = 0; i < 4; i++) {
            float s = 0.f;
            #pragma unroll
            for (int q = 0; q < 4; q++) {
                int c = tx * 4 + q * 64;
                float x0, x1, x2, x3;
                unpack_f32x2(acc[i][2 * q + 0], x0, x1);
                unpack_f32x2(acc[i][2 * q + 1], x2, x3);
                s += fmaxf(x0 + bias[c + 0], 0.f) * whead[c + 0];
                s += fmaxf(x1 + bias[c + 1], 0.f) * whead[c + 1];
                s += fmaxf(x2 + bias[c + 2], 0.f) * whead[c + 2];
                s += fmaxf(x3 + bias[c + 3], 0.f) * whead[c + 3];
            }
            #pragma unroll
            for (int off = 8; off; off >>= 1)
                s += __shfl_xor_sync(0xffffffffu, s, off);
            int row = bm0 + ty * 4 + i;
            if (tx == 0 && row < N_NODES) head_out[row] = s + bhead[0];
        }
    }
}

// ---------------- launcher ----------------
extern "C" void kernel_launch(void* const* d_in, const int* in_sizes, int n_in,
                              void* d_out, int out_size) {
    const float* x   = (const float*)d_in[0];
    const void*  ei  = d_in[1];
    const float *Wl1 = (const float*)d_in[2],  *bl1 = (const float*)d_in[3],
                *Wr1 = (const float*)d_in[4];
    const float *Wl2 = (const float*)d_in[5],  *bl2 = (const float*)d_in[6],
                *Wr2 = (const float*)d_in[7];
    const float *Wla = (const float*)d_in[8],  *bla = (const float*)d_in[9],
                *Wra = (const float*)d_in[10], *Wa  = (const float*)d_in[11],
                *ba  = (const float*)d_in[12];
    const float *Wlm = (const float*)d_in[13], *blm = (const float*)d_in[14],
                *Wrm = (const float*)d_in[15], *Wm  = (const float*)d_in[16],
                *bm  = (const float*)d_in[17];
    float* out = (float*)d_out;

    float *agg, *h1, *h2;
    cudaGetSymbolAddress((void**)&agg, g_agg);
    cudaGetSymbolAddress((void**)&h1,  g_h1);
    cudaGetSymbolAddress((void**)&h2,  g_h2);

    const int GEMM_GRID = (N_NODES + BM - 1) / BM;   // 782
    const int SEG1_GRID = (N_NODES + 7) / 8;         // F=128: 8 nodes/block
    const int SEG2_GRID = (N_NODES + 3) / 4;         // F=256: 4 nodes/block

    // CSR build (launch order chosen so ncu -s 5 captures the first GEMM)
    init_kernel<<<SCAN_BLOCKS, 1024>>>(ei);                       // 0
    hist_kernel<<<(E_EDGES + 511) / 512, 512>>>(ei);              // 1
    scan_kernel<<<SCAN_BLOCKS, 1024>>>();                         // 2
    scatter_kernel<<<(E_EDGES + 511) / 512, 512>>>(ei);           // 3

    // layer 1
    segmax_kernel<F_IN><<<SEG1_GRID, 256>>>((const float4*)x, (float4*)agg);  // 4
    sage_gemm_kernel<<<GEMM_GRID, 256>>>(agg, x, Wl1, Wr1, bl1, F_IN,         // 5
                                         h1, nullptr, nullptr, nullptr);
    // layer 2
    segmax_kernel<HID><<<SEG2_GRID, 256>>>((const float4*)h1, (float4*)agg);
    sage_gemm_kernel<<<GEMM_GRID, 256>>>(agg, h1, Wl2, Wr2, bl2, HID,
                                         h2, nullptr, nullptr, nullptr);
    // layer 3 aggregation shared by both heads
    segmax_kernel<HID><<<SEG2_GRID, 256>>>((const float4*)h2, (float4*)agg);
    sage_gemm_kernel<<<GEMM_GRID, 256>>>(agg, h2, Wla, Wra, bla, HID,
                                         nullptr, Wa, ba, out);
    sage_gemm_kernel<<<GEMM_GRID, 256>>>(agg, h2, Wlm, Wrm, blm, HID,
                                         nullptr, Wm, bm, out + N_NODES);
}

// round 9
// speedup vs baseline: 2.7267x; 1.0070x over previous
#include <cuda_runtime.h>
#include <cuda_bf16.h>
#include <cstdint>

#define N_NODES 50000
#define E_EDGES 800000
#define F_IN    128
#define HID     256

#define SCAN_BLOCKS 49   // ceil(50000/1024)

// ---------------- scratch (static __device__, no allocation) ----------------
__device__ float g_agg[(size_t)N_NODES * HID];
__device__ float g_h1 [(size_t)N_NODES * HID];
__device__ float g_h2 [(size_t)N_NODES * HID];
__device__ int   g_deg[N_NODES];
__device__ int   g_rowptr[N_NODES + 1];
__device__ int   g_cursor[N_NODES];
__device__ int   g_csrsrc[E_EDGES];
__device__ int   g_is64;
__device__ int   g_flag[SCAN_BLOCKS + 1];
__device__ int   g_pref[SCAN_BLOCKS + 1];

// ---------------- helpers ----------------
__device__ __forceinline__ unsigned long long dup_f32(float v) {
    unsigned long long d;
    asm("mov.b64 %0, {%1,%1};" : "=l"(d) : "f"(v));
    return d;
}
__device__ __forceinline__ void unpack_f32x2(unsigned long long v, float& lo, float& hi) {
    asm("mov.b64 {%0,%1}, %2;" : "=f"(lo), "=f"(hi) : "l"(v));
}
__device__ __forceinline__ void fma2(unsigned long long& d,
                                     unsigned long long a, unsigned long long b) {
    asm("fma.rn.f32x2 %0, %1, %2, %0;" : "+l"(d) : "l"(a), "l"(b));
}
__device__ __forceinline__ long long load_edge(const void* ei, int idx) {
    if (g_is64) return ((const long long*)ei)[idx];
    return (long long)((const int*)ei)[idx];
}

// ---------------- init: zero deg + flags, detect edge dtype ----------------
__global__ void init_kernel(const void* ei) {
    int i = blockIdx.x * blockDim.x + threadIdx.x;
    if (i < N_NODES) g_deg[i] = 0;
    if (i <= SCAN_BLOCKS) { g_flag[i] = 0; g_pref[i] = 0; }
    if (i == 0) {
        const long long* p = (const long long*)ei;
        int ok = 1;
        for (int k = 0; k < 128; k++) {
            long long v = p[k];
            if (v < 0 || v >= N_NODES) { ok = 0; break; }
        }
        g_is64 = ok;
    }
}

__global__ void hist_kernel(const void* ei) {
    int e = blockIdx.x * blockDim.x + threadIdx.x;
    if (e < E_EDGES) {
        int d = (int)load_edge(ei, E_EDGES + e);
        atomicAdd(&g_deg[d], 1);
    }
}

// ---------------- chained multi-block exclusive scan (49 blocks x 1024) -----
__global__ __launch_bounds__(1024)
void scan_kernel() {
    __shared__ int wsum[32];
    __shared__ int s_pref;
    int tid = threadIdx.x, b = blockIdx.x;
    int wid = tid >> 5, lane = tid & 31;
    int i = b * 1024 + tid;
    int v = (i < N_NODES) ? g_deg[i] : 0;

    int incl = v;
    #pragma unroll
    for (int off = 1; off < 32; off <<= 1) {
        int t = __shfl_up_sync(0xffffffffu, incl, off);
        if (lane >= off) incl += t;
    }
    if (lane == 31) wsum[wid] = incl;
    __syncthreads();
    if (tid < 32) {
        int x = wsum[tid];
        #pragma unroll
        for (int off = 1; off < 32; off <<= 1) {
            int t = __shfl_up_sync(0xffffffffu, x, off);
            if (tid >= off) x += t;
        }
        wsum[tid] = x;           // inclusive over warp sums
    }
    __syncthreads();
    int excl = (wid ? wsum[wid - 1] : 0) + incl - v;

    if (tid == 0) {
        int total = wsum[31];
        int p = 0;
        if (b > 0) {
            while (atomicAdd(&g_flag[b - 1], 0) == 0) { }
            p = *((volatile int*)&g_pref[b - 1]);
        }
        *((volatile int*)&g_pref[b]) = p + total;
        __threadfence();
        atomicExch(&g_flag[b], 1);
        s_pref = p;
    }
    __syncthreads();
    if (i < N_NODES) {
        int r = s_pref + excl;
        g_rowptr[i] = r;
        g_cursor[i] = r;
    }
    if (b == 0 && tid == 0) g_rowptr[N_NODES] = E_EDGES;
}

__global__ void scatter_kernel(const void* ei) {
    int e = blockIdx.x * blockDim.x + threadIdx.x;
    if (e < E_EDGES) {
        int s = (int)load_edge(ei, e);
        int d = (int)load_edge(ei, E_EDGES + e);
        int p = atomicAdd(&g_cursor[d], 1);
        g_csrsrc[p] = s;
    }
}

// ---------------- segment max, float4 vectorized ----------------------------
// tpn = F/4 threads per node; 256-thread blocks handle 256/tpn nodes each.
template<int F>
__global__ __launch_bounds__(256)
void segmax_kernel(const float4* __restrict__ in, float4* __restrict__ out) {
    const int TPN = F / 4;
    const int NPB = 256 / TPN;
    int node = blockIdx.x * NPB + threadIdx.x / TPN;
    int lane = threadIdx.x % TPN;
    if (node >= N_NODES) return;
    int s = g_rowptr[node];
    int t = g_rowptr[node + 1];
    const float NEG = -3.402823466e+38f;
    float4 m = make_float4(NEG, NEG, NEG, NEG);
    int j = s;
    for (; j + 4 <= t; j += 4) {
        int u0 = g_csrsrc[j + 0];
        int u1 = g_csrsrc[j + 1];
        int u2 = g_csrsrc[j + 2];
        int u3 = g_csrsrc[j + 3];
        float4 v0 = in[(size_t)u0 * TPN + lane];
        float4 v1 = in[(size_t)u1 * TPN + lane];
        float4 v2 = in[(size_t)u2 * TPN + lane];
        float4 v3 = in[(size_t)u3 * TPN + lane];
        m.x = fmaxf(m.x, fmaxf(fmaxf(v0.x, v1.x), fmaxf(v2.x, v3.x)));
        m.y = fmaxf(m.y, fmaxf(fmaxf(v0.y, v1.y), fmaxf(v2.y, v3.y)));
        m.z = fmaxf(m.z, fmaxf(fmaxf(v0.z, v1.z), fmaxf(v2.z, v3.z)));
        m.w = fmaxf(m.w, fmaxf(fmaxf(v0.w, v1.w), fmaxf(v2.w, v3.w)));
    }
    for (; j < t; j++) {
        int u = g_csrsrc[j];
        float4 v = in[(size_t)u * TPN + lane];
        m.x = fmaxf(m.x, v.x); m.y = fmaxf(m.y, v.y);
        m.z = fmaxf(m.z, v.z); m.w = fmaxf(m.w, v.w);
    }
    if (t <= s) m = make_float4(0.f, 0.f, 0.f, 0.f);
    out[(size_t)node * TPN + lane] = m;
}

// ---------------- fused SAGE GEMM: out = relu(Aagg@Bl + Ax@Br + bias) -------
// BM=64 x BN=256 (full H), BK=16, 256 threads (16x16).
// Per-thread columns: tx*4 + q*64 (q=0..3) -> conflict-free LDS.128 on Bs.
// head mode: feat_out==nullptr; head_out[row] = relu_feat . whead + bhead.
#define BM 64
#define BN 256
#define BK 16

__global__ __launch_bounds__(256)
void sage_gemm_kernel(const float* __restrict__ Aagg, const float* __restrict__ Ax,
                      const float* __restrict__ Bl,   const float* __restrict__ Br,
                      const float* __restrict__ bias, int K,
                      float* __restrict__ feat_out,
                      const float* __restrict__ whead,
                      const float* __restrict__ bhead,
                      float* __restrict__ head_out) {
    __shared__ __align__(16) unsigned long long As2[BK][BM];  // dup-packed A
    __shared__ __align__(16) float Bs[BK][BN];

    int tid = threadIdx.x;
    int tx = tid & 15, ty = tid >> 4;
    int bm0 = blockIdx.x * BM;

    unsigned long long acc[4][8];
    #pragma unroll
    for (int i = 0; i < 4; i++)
        #pragma unroll
        for (int j = 0; j < 8; j++) acc[i][j] = 0ULL;

    int am = tid >> 2;            // 0..63 row in A tile
    int ak = (tid & 3) * 4;       // k offset in A tile
    int bk = tid >> 4;            // 0..15 k row in B tile
    int bc = (tid & 15) * 4;      // col base in B tile

    for (int pass = 0; pass < 2; ++pass) {
        const float* A = pass ? Ax : Aagg;
        const float* B = pass ? Br : Bl;
        for (int kt = 0; kt < K; kt += BK) {
            float4 av = make_float4(0.f, 0.f, 0.f, 0.f);
            int row = bm0 + am;
            if (row < N_NODES)
                av = *(const float4*)&A[(size_t)row * K + kt + ak];
            As2[ak + 0][am] = dup_f32(av.x);
            As2[ak + 1][am] = dup_f32(av.y);
            As2[ak + 2][am] = dup_f32(av.z);
            As2[ak + 3][am] = dup_f32(av.w);
            #pragma unroll
            for (int q = 0; q < 4; q++)
                *(float4*)&Bs[bk][bc + q * 64] =
                    *(const float4*)&B[(size_t)(kt + bk) * 256 + bc + q * 64];
            __syncthreads();

            #pragma unroll
            for (int kk = 0; kk < BK; kk++) {
                unsigned long long b[8];
                #pragma unroll
                for (int q = 0; q < 4; q++) {
                    ulonglong2 t = *(const ulonglong2*)&Bs[kk][tx * 4 + q * 64];
                    b[2 * q + 0] = t.x;
                    b[2 * q + 1] = t.y;
                }
                const ulonglong2* ap = (const ulonglong2*)&As2[kk][ty * 4];
                ulonglong2 a01 = ap[0], a23 = ap[1];
                unsigned long long a[4] = {a01.x, a01.y, a23.x, a23.y};
                #pragma unroll
                for (int i = 0; i < 4; i++)
                    #pragma unroll
                    for (int j = 0; j < 8; j++)
                        fma2(acc[i][j], a[i], b[j]);
            }
            __syncthreads();
        }
    }

    if (whead == nullptr) {
        #pragma unroll
        for (int i = 0; i < 4; i++) {
            int row = bm0 + ty * 4 + i;
            if (row >= N_NODES) continue;
            #pragma unroll
            for (int q = 0; q < 4; q++) {
                int c = tx * 4 + q * 64;
                float x0, x1, x2, x3;
                unpack_f32x2(acc[i][2 * q + 0], x0, x1);
                unpack_f32x2(acc[i][2 * q + 1], x2, x3);
                float4 o;
                o.x = fmaxf(x0 + bias[c + 0], 0.f);
                o.y = fmaxf(x1 + bias[c + 1], 0.f);
                o.z = fmaxf(x2 + bias[c + 2], 0.f);
                o.w = fmaxf(x3 + bias[c + 3], 0.f);
                *(float4*)&feat_out[(size_t)row * 256 + c] = o;
            }
        }
    } else {
        #pragma unroll
        for (int i = 0; i < 4; i++) {
            float s = 0.f;
            #pragma unroll
            for (int q = 0; q < 4; q++) {
                int c = tx * 4 + q * 64;
                float x0, x1, x2, x3;
                unpack_f32x2(acc[i][2 * q + 0], x0, x1);
                unpack_f32x2(acc[i][2 * q + 1], x2, x3);
                s += fmaxf(x0 + bias[c + 0], 0.f) * whead[c + 0];
                s += fmaxf(x1 + bias[c + 1], 0.f) * whead[c + 1];
                s += fmaxf(x2 + bias[c + 2], 0.f) * whead[c + 2];
                s += fmaxf(x3 + bias[c + 3], 0.f) * whead[c + 3];
            }
            #pragma unroll
            for (int off = 8; off; off >>= 1)
                s += __shfl_xor_sync(0xffffffffu, s, off);
            int row = bm0 + ty * 4 + i;
            if (tx == 0 && row < N_NODES) head_out[row] = s + bhead[0];
        }
    }
}

// ---------------- launcher ----------------
extern "C" void kernel_launch(void* const* d_in, const int* in_sizes, int n_in,
                              void* d_out, int out_size) {
    const float* x   = (const float*)d_in[0];
    const void*  ei  = d_in[1];
    const float *Wl1 = (const float*)d_in[2],  *bl1 = (const float*)d_in[3],
                *Wr1 = (const float*)d_in[4];
    const float *Wl2 = (const float*)d_in[5],  *bl2 = (const float*)d_in[6],
                *Wr2 = (const float*)d_in[7];
    const float *Wla = (const float*)d_in[8],  *bla = (const float*)d_in[9],
                *Wra = (const float*)d_in[10], *Wa  = (const float*)d_in[11],
                *ba  = (const float*)d_in[12];
    const float *Wlm = (const float*)d_in[13], *blm = (const float*)d_in[14],
                *Wrm = (const float*)d_in[15], *Wm  = (const float*)d_in[16],
                *bm  = (const float*)d_in[17];
    float* out = (float*)d_out;

    float *agg, *h1, *h2;
    cudaGetSymbolAddress((void**)&agg, g_agg);
    cudaGetSymbolAddress((void**)&h1,  g_h1);
    cudaGetSymbolAddress((void**)&h2,  g_h2);

    const int GEMM_GRID = (N_NODES + BM - 1) / BM;   // 782
    const int SEG1_GRID = (N_NODES + 7) / 8;         // F=128: 8 nodes/block
    const int SEG2_GRID = (N_NODES + 3) / 4;         // F=256: 4 nodes/block

    // CSR build (launch order chosen so ncu -s 5 captures the first GEMM)
    init_kernel<<<SCAN_BLOCKS, 1024>>>(ei);                       // 0
    hist_kernel<<<(E_EDGES + 511) / 512, 512>>>(ei);              // 1
    scan_kernel<<<SCAN_BLOCKS, 1024>>>();                         // 2
    scatter_kernel<<<(E_EDGES + 511) / 512, 512>>>(ei);           // 3

    // layer 1
    segmax_kernel<F_IN><<<SEG1_GRID, 256>>>((const float4*)x, (float4*)agg);  // 4
    sage_gemm_kernel<<<GEMM_GRID, 256>>>(agg, x, Wl1, Wr1, bl1, F_IN,         // 5
                                         h1, nullptr, nullptr, nullptr);
    // layer 2
    segmax_kernel<HID><<<SEG2_GRID, 256>>>((const float4*)h1, (float4*)agg);
    sage_gemm_kernel<<<GEMM_GRID, 256>>>(agg, h1, Wl2, Wr2, bl2, HID,
                                         h2, nullptr, nullptr, nullptr);
    // layer 3 aggregation shared by both heads
    segmax_kernel<HID><<<SEG2_GRID, 256>>>((const float4*)h2, (float4*)agg);
    sage_gemm_kernel<<<GEMM_GRID, 256>>>(agg, h2, Wla, Wra, bla, HID,
                                         nullptr, Wa, ba, out);
    sage_gemm_kernel<<<GEMM_GRID, 256>>>(agg, h2, Wlm, Wrm, blm, HID,
                                         nullptr, Wm, bm, out + N_NODES);
}

// round 12
// speedup vs baseline: 4.7226x; 1.7320x over previous
#include <cuda_runtime.h>
#include <cuda_bf16.h>
#include <cstdint>

using bf16 = __nv_bfloat16;

#define N_NODES 50000
#define E_EDGES 800000
#define F_IN    128
#define HID     256
#define SCAN_BLOCKS 49

__device__ float g_agg[(size_t)N_NODES * HID];
__device__ float g_h1 [(size_t)N_NODES * HID];
__device__ float g_h2 [(size_t)N_NODES * HID];
__device__ bf16  g_wthi[458752];
__device__ bf16  g_wtlo[458752];
__device__ int   g_deg[N_NODES];
__device__ int   g_rowptr[N_NODES + 1];
__device__ int   g_cursor[N_NODES];
__device__ int   g_csrsrc[E_EDGES];
__device__ int   g_flag[SCAN_BLOCKS + 1];
__device__ int   g_pref[SCAN_BLOCKS + 1];

// ---------------- PTX helpers ----------------
__device__ __forceinline__ uint32_t smem_u32(const void* p) {
    uint32_t a;
    asm("{ .reg .u64 t; cvta.to.shared.u64 t, %1; cvt.u32.u64 %0, t; }" : "=r"(a) : "l"(p));
    return a;
}
__device__ __forceinline__ void ldsm4(uint32_t* r, uint32_t addr) {
    asm volatile("ldmatrix.sync.aligned.m8n8.x4.shared.b16 {%0,%1,%2,%3}, [%4];"
                 : "=r"(r[0]), "=r"(r[1]), "=r"(r[2]), "=r"(r[3]) : "r"(addr));
}
__device__ __forceinline__ void mma_bf16(float* c, const uint32_t* a, const uint32_t* b) {
    asm volatile("mma.sync.aligned.m16n8k16.row.col.f32.bf16.bf16.f32 "
                 "{%0,%1,%2,%3}, {%4,%5,%6,%7}, {%8,%9}, {%0,%1,%2,%3};"
                 : "+f"(c[0]), "+f"(c[1]), "+f"(c[2]), "+f"(c[3])
                 : "r"(a[0]), "r"(a[1]), "r"(a[2]), "r"(a[3]), "r"(b[0]), "r"(b[1]));
}

// ---------------- CSR build ----------------
__device__ __forceinline__ int detect_is64(const void* ei) {
    __shared__ int s64;
    if (threadIdx.x == 0) {
        const long long* p = (const long long*)ei;
        int ok = 1;
        #pragma unroll 1
        for (int k = 0; k < 128; k++) {
            long long v = p[k];
            if (v < 0 || v >= N_NODES) { ok = 0; break; }
        }
        s64 = ok;
    }
    __syncthreads();
    return s64;
}
__device__ __forceinline__ int load_edge(const void* ei, int idx, int is64) {
    return is64 ? (int)((const long long*)ei)[idx] : ((const int*)ei)[idx];
}

__global__ void hist_kernel(const void* ei) {
    int is64 = detect_is64(ei);
    int e = blockIdx.x * blockDim.x + threadIdx.x;
    if (e < E_EDGES) atomicAdd(&g_deg[load_edge(ei, E_EDGES + e, is64)], 1);
}

__global__ __launch_bounds__(1024)
void scan_kernel() {
    __shared__ int wsum[32];
    __shared__ int s_pref;
    int tid = threadIdx.x, b = blockIdx.x, wid = tid >> 5, lane = tid & 31;
    int i = b * 1024 + tid;
    int v = (i < N_NODES) ? g_deg[i] : 0;
    int incl = v;
    #pragma unroll
    for (int off = 1; off < 32; off <<= 1) {
        int t = __shfl_up_sync(~0u, incl, off);
        if (lane >= off) incl += t;
    }
    if (lane == 31) wsum[wid] = incl;
    __syncthreads();
    if (tid < 32) {
        int x = wsum[tid];
        #pragma unroll
        for (int off = 1; off < 32; off <<= 1) {
            int t = __shfl_up_sync(~0u, x, off);
            if (tid >= off) x += t;
        }
        wsum[tid] = x;
    }
    __syncthreads();
    int excl = (wid ? wsum[wid - 1] : 0) + incl - v;
    if (tid == 0) {
        int total = wsum[31], p = 0;
        if (b > 0) {
            while (atomicAdd(&g_flag[b - 1], 0) == 0) { }
            p = *((volatile int*)&g_pref[b - 1]);
        }
        *((volatile int*)&g_pref[b]) = p + total;
        __threadfence();
        atomicExch(&g_flag[b], 1);
        s_pref = p;
    }
    __syncthreads();
    if (i < N_NODES) { int r = s_pref + excl; g_rowptr[i] = r; g_cursor[i] = r; }
    if (b == 0 && tid == 0) g_rowptr[N_NODES] = E_EDGES;
}

__global__ void scatter_kernel(const void* ei) {
    int is64 = detect_is64(ei);
    int e = blockIdx.x * blockDim.x + threadIdx.x;
    if (e < E_EDGES) {
        int s = load_edge(ei, e, is64);
        int d = load_edge(ei, E_EDGES + e, is64);
        g_csrsrc[atomicAdd(&g_cursor[d], 1)] = s;
    }
}

__global__ void reset_kernel() {   // state is zero at module load; re-zero per replay
    int i = blockIdx.x * blockDim.x + threadIdx.x;
    if (i < N_NODES) g_deg[i] = 0;
    if (i <= SCAN_BLOCKS) { g_flag[i] = 0; g_pref[i] = 0; }
}

// ---------------- weight transpose + hi/lo split ([n][k], k contiguous) -----
struct ConvW { const float* W[8]; int off[8]; int K[8]; };
__global__ void conv_w_kernel(ConvW P) {
    int mat = blockIdx.z, Kd = P.K[mat];
    if ((int)blockIdx.y * 32 >= Kd) return;
    __shared__ float t[32][33];
    int n0 = blockIdx.x * 32, k0 = blockIdx.y * 32;
    #pragma unroll
    for (int q = 0; q < 4; q++)
        t[threadIdx.y + q * 8][threadIdx.x] =
            P.W[mat][(size_t)(k0 + threadIdx.y + q * 8) * 256 + n0 + threadIdx.x];
    __syncthreads();
    #pragma unroll
    for (int q = 0; q < 4; q++) {
        int n = n0 + threadIdx.y + q * 8, k = k0 + threadIdx.x;
        float v = t[threadIdx.x][threadIdx.y + q * 8];
        bf16 h = __float2bfloat16(v);
        g_wthi[P.off[mat] + (size_t)n * Kd + k] = h;
        g_wtlo[P.off[mat] + (size_t)n * Kd + k] = __float2bfloat16(v - __bfloat162float(h));
    }
}

// ---------------- segment max (fp32, float4) ----------------
template<int F>
__global__ __launch_bounds__(256)
void segmax_kernel(const float4* __restrict__ in, float4* __restrict__ out) {
    const int TPN = F / 4;
    int node = blockIdx.x * (256 / TPN) + threadIdx.x / TPN;
    int lane = threadIdx.x % TPN;
    if (node >= N_NODES) return;
    int s = g_rowptr[node], t = g_rowptr[node + 1];
    const float NEG = -3.402823466e+38f;
    float4 m = make_float4(NEG, NEG, NEG, NEG);
    int j = s;
    for (; j + 4 <= t; j += 4) {
        int u0 = g_csrsrc[j], u1 = g_csrsrc[j + 1], u2 = g_csrsrc[j + 2], u3 = g_csrsrc[j + 3];
        float4 v0 = in[(size_t)u0 * TPN + lane], v1 = in[(size_t)u1 * TPN + lane];
        float4 v2 = in[(size_t)u2 * TPN + lane], v3 = in[(size_t)u3 * TPN + lane];
        m.x = fmaxf(m.x, fmaxf(fmaxf(v0.x, v1.x), fmaxf(v2.x, v3.x)));
        m.y = fmaxf(m.y, fmaxf(fmaxf(v0.y, v1.y), fmaxf(v2.y, v3.y)));
        m.z = fmaxf(m.z, fmaxf(fmaxf(v0.z, v1.z), fmaxf(v2.z, v3.z)));
        m.w = fmaxf(m.w, fmaxf(fmaxf(v0.w, v1.w), fmaxf(v2.w, v3.w)));
    }
    for (; j < t; j++) {
        float4 v = in[(size_t)g_csrsrc[j] * TPN + lane];
        m.x = fmaxf(m.x, v.x); m.y = fmaxf(m.y, v.y);
        m.z = fmaxf(m.z, v.z); m.w = fmaxf(m.w, v.w);
    }
    if (t <= s) m = make_float4(0.f, 0.f, 0.f, 0.f);
    out[(size_t)node * TPN + lane] = m;
}

// ---------------- HMMA split-precision SAGE GEMM ----------------------------
// h = relu(Aagg@Wl + Ax@Wr + bias); D = Ahi*Bhi + Alo*Bhi + Ahi*Blo (fp32 acc)
// CTA 128x64, 8 warps (4m x 2n), warp 32x32, BK=32. SMEM stride 40 bf16 (80B,
// conflict-free for ldmatrix: r*80 mod 128 all distinct).
#define ASTR 40
template<int KD>
__global__ __launch_bounds__(256)
void gemm_kernel(const float* __restrict__ Aagg, const float* __restrict__ Ax,
                 const bf16* __restrict__ BlHi, const bf16* __restrict__ BlLo,
                 const bf16* __restrict__ BrHi, const bf16* __restrict__ BrLo,
                 const float* __restrict__ bias, float* __restrict__ h32) {
    __shared__ __align__(16) bf16 sAh[128 * ASTR];
    __shared__ __align__(16) bf16 sAl[128 * ASTR];
    __shared__ __align__(16) bf16 sBh[64 * ASTR];
    __shared__ __align__(16) bf16 sBl[64 * ASTR];

    const int tid = threadIdx.x, lane = tid & 31, wid = tid >> 5;
    const int wm = wid & 3, wn = wid >> 2;
    const int bm0 = blockIdx.x * 128, n0 = blockIdx.y * 64;
    const uint32_t aBase = smem_u32(sAh), alBase = smem_u32(sAl);
    const uint32_t bBase = smem_u32(sBh), blBase = smem_u32(sBl);

    float acc[2][4][4];
    #pragma unroll
    for (int i = 0; i < 2; i++)
        #pragma unroll
        for (int j = 0; j < 4; j++)
            #pragma unroll
            for (int v = 0; v < 4; v++) acc[i][j][v] = 0.f;

    // ldmatrix source addresses (bytes)
    const uint32_t aRow = wm * 32 + (lane & 15), aCol = (lane >> 4) * 8;
    const uint32_t bRow = wn * 32 + ((lane >> 4) << 3) + (lane & 7);
    const uint32_t bCol = ((lane >> 3) & 1) * 8;

    #pragma unroll 1
    for (int pass = 0; pass < 2; pass++) {
        const float* A = pass ? Ax : Aagg;
        const bf16* Bh = pass ? BrHi : BlHi;
        const bf16* Bl = pass ? BrLo : BlLo;
        #pragma unroll 1
        for (int kt = 0; kt < KD; kt += 32) {
            // A: 128x32 fp32 -> hi/lo bf16
            #pragma unroll
            for (int q = 0; q < 4; q++) {
                int idx = tid + q * 256;           // 1024 float4 slots
                int row = idx >> 3, kg = (idx & 7) * 4;
                int r = bm0 + row;
                float4 v = (r < N_NODES) ? *(const float4*)&A[(size_t)r * KD + kt + kg]
                                         : make_float4(0.f, 0.f, 0.f, 0.f);
                bf16 h0 = __float2bfloat16(v.x), h1 = __float2bfloat16(v.y);
                bf16 h2 = __float2bfloat16(v.z), h3 = __float2bfloat16(v.w);
                __nv_bfloat162 hp0{h0, h1}, hp1{h2, h3};
                __nv_bfloat162 lp0{__float2bfloat16(v.x - __bfloat162float(h0)),
                                   __float2bfloat16(v.y - __bfloat162float(h1))};
                __nv_bfloat162 lp1{__float2bfloat16(v.z - __bfloat162float(h2)),
                                   __float2bfloat16(v.w - __bfloat162float(h3))};
                *(uint2*)&sAh[row * ASTR + kg] = make_uint2(*(uint32_t*)&hp0, *(uint32_t*)&hp1);
                *(uint2*)&sAl[row * ASTR + kg] = make_uint2(*(uint32_t*)&lp0, *(uint32_t*)&lp1);
            }
            // B: 64x32 bf16 hi/lo (weights pre-transposed [n][k])
            {
                int row = tid >> 2, kg = (tid & 3) * 8;
                const uint4 vh = *(const uint4*)&Bh[(size_t)(n0 + row) * KD + kt + kg];
                const uint4 vl = *(const uint4*)&Bl[(size_t)(n0 + row) * KD + kt + kg];
                *(uint2*)&sBh[row * ASTR + kg]     = make_uint2(vh.x, vh.y);
                *(uint2*)&sBh[row * ASTR + kg + 4] = make_uint2(vh.z, vh.w);
                *(uint2*)&sBl[row * ASTR + kg]     = make_uint2(vl.x, vl.y);
                *(uint2*)&sBl[row * ASTR + kg + 4] = make_uint2(vl.z, vl.w);
            }
            __syncthreads();

            #pragma unroll
            for (int ks = 0; ks < 2; ks++) {
                uint32_t ah[2][4], al[2][4], bh[8], bl[8];
                #pragma unroll
                for (int i = 0; i < 2; i++) {
                    uint32_t off = ((aRow + i * 16) * ASTR + ks * 16 + aCol) * 2;
                    ldsm4(ah[i], aBase + off);
                    ldsm4(al[i], alBase + off);
                }
                #pragma unroll
                for (int jp = 0; jp < 2; jp++) {
                    uint32_t off = ((bRow + jp * 16) * ASTR + ks * 16 + bCol) * 2;
                    ldsm4(&bh[jp * 4], bBase + off);
                    ldsm4(&bl[jp * 4], blBase + off);
                }
                #pragma unroll
                for (int i = 0; i < 2; i++)
                    #pragma unroll
                    for (int j = 0; j < 4; j++) {
                        mma_bf16(acc[i][j], ah[i], &bh[j * 2]);
                        mma_bf16(acc[i][j], al[i], &bh[j * 2]);
                        mma_bf16(acc[i][j], ah[i], &bl[j * 2]);
                    }
            }
            __syncthreads();
        }
    }

    // epilogue: bias + relu, float2 stores
    #pragma unroll
    for (int i = 0; i < 2; i++) {
        #pragma unroll
        for (int j = 0; j < 4; j++) {
            int col = n0 + wn * 32 + j * 8 + (lane & 3) * 2;
            float b0 = bias[col], b1 = bias[col + 1];
            int r0 = bm0 + wm * 32 + i * 16 + (lane >> 2);
            if (r0 < N_NODES) {
                float2 o0;
                o0.x = fmaxf(acc[i][j][0] + b0, 0.f);
                o0.y = fmaxf(acc[i][j][1] + b1, 0.f);
                *(float2*)&h32[(size_t)r0 * 256 + col] = o0;
            }
            int r1 = r0 + 8;
            if (r1 < N_NODES) {
                float2 o1;
                o1.x = fmaxf(acc[i][j][2] + b0, 0.f);
                o1.y = fmaxf(acc[i][j][3] + b1, 0.f);
                *(float2*)&h32[(size_t)r1 * 256 + col] = o1;
            }
        }
    }
}

// ---------------- head dot: out[r] = feat[r,:] . w + b (feat already relu) --
__global__ __launch_bounds__(256)
void head_dot_kernel(const float4* __restrict__ feat, const float* __restrict__ w,
                     const float* __restrict__ b, float* __restrict__ out) {
    int wid = threadIdx.x >> 5, lane = threadIdx.x & 31;
    int row = blockIdx.x * 8 + wid;
    if (row >= N_NODES) return;
    const float4* fr = feat + (size_t)row * 64;
    const float4* w4 = (const float4*)w;
    float s = 0.f;
    #pragma unroll
    for (int q = 0; q < 2; q++) {
        float4 f = fr[lane + q * 32];
        float4 ww = w4[lane + q * 32];
        s += f.x * ww.x + f.y * ww.y + f.z * ww.z + f.w * ww.w;
    }
    #pragma unroll
    for (int off = 16; off; off >>= 1) s += __shfl_xor_sync(~0u, s, off);
    if (lane == 0) out[row] = s + b[0];
}

// ---------------- launcher ----------------
extern "C" void kernel_launch(void* const* d_in, const int* in_sizes, int n_in,
                              void* d_out, int out_size) {
    const float* x   = (const float*)d_in[0];
    const void*  ei  = d_in[1];
    const float *Wl1 = (const float*)d_in[2],  *bl1 = (const float*)d_in[3],
                *Wr1 = (const float*)d_in[4];
    const float *Wl2 = (const float*)d_in[5],  *bl2 = (const float*)d_in[6],
                *Wr2 = (const float*)d_in[7];
    const float *Wla = (const float*)d_in[8],  *bla = (const float*)d_in[9],
                *Wra = (const float*)d_in[10], *Wa  = (const float*)d_in[11],
                *ba  = (const float*)d_in[12];
    const float *Wlm = (const float*)d_in[13], *blm = (const float*)d_in[14],
                *Wrm = (const float*)d_in[15], *Wm  = (const float*)d_in[16],
                *bm  = (const float*)d_in[17];
    float* out = (float*)d_out;

    float *agg, *h1, *h2;
    bf16 *whi, *wlo;
    cudaGetSymbolAddress((void**)&agg, g_agg);
    cudaGetSymbolAddress((void**)&h1,  g_h1);
    cudaGetSymbolAddress((void**)&h2,  g_h2);
    cudaGetSymbolAddress((void**)&whi, g_wthi);
    cudaGetSymbolAddress((void**)&wlo, g_wtlo);

    const int oL1 = 0, oR1 = 32768, oL2 = 65536, oR2 = 131072,
              oLA = 196608, oRA = 262144, oLM = 327680, oRM = 393216;
    ConvW cw;
    cw.W[0] = Wl1; cw.W[1] = Wr1; cw.W[2] = Wl2; cw.W[3] = Wr2;
    cw.W[4] = Wla; cw.W[5] = Wra; cw.W[6] = Wlm; cw.W[7] = Wrm;
    cw.off[0] = oL1; cw.off[1] = oR1; cw.off[2] = oL2; cw.off[3] = oR2;
    cw.off[4] = oLA; cw.off[5] = oRA; cw.off[6] = oLM; cw.off[7] = oRM;
    cw.K[0] = 128; cw.K[1] = 128;
    for (int i = 2; i < 8; i++) cw.K[i] = 256;

    const int SEG1 = (N_NODES + 7) / 8, SEG2 = (N_NODES + 3) / 4;
    const dim3 GG((N_NODES + 127) / 128, 4);   // 391 x 4 n-slabs of 64
    const int HD = (N_NODES + 7) / 8;

    hist_kernel<<<(E_EDGES + 511) / 512, 512>>>(ei);                   // 0
    scan_kernel<<<SCAN_BLOCKS, 1024>>>();                              // 1
    scatter_kernel<<<(E_EDGES + 511) / 512, 512>>>(ei);                // 2
    conv_w_kernel<<<dim3(8, 8, 8), dim3(32, 8)>>>(cw);                 // 3

    segmax_kernel<F_IN><<<SEG1, 256>>>((const float4*)x, (float4*)agg);          // 4
    gemm_kernel<128><<<GG, 256>>>(agg, x, whi + oL1, wlo + oL1,                  // 5
                                  whi + oR1, wlo + oR1, bl1, h1);
    segmax_kernel<HID><<<SEG2, 256>>>((const float4*)h1, (float4*)agg);
    gemm_kernel<256><<<GG, 256>>>(agg, h1, whi + oL2, wlo + oL2,
                                  whi + oR2, wlo + oR2, bl2, h2);
    segmax_kernel<HID><<<SEG2, 256>>>((const float4*)h2, (float4*)agg);
    gemm_kernel<256><<<GG, 256>>>(agg, h2, whi + oLA, wlo + oLA,
                                  whi + oRA, wlo + oRA, bla, h1);
    head_dot_kernel<<<HD, 256>>>((const float4*)h1, Wa, ba, out);
    gemm_kernel<256><<<GG, 256>>>(agg, h2, whi + oLM, wlo + oLM,
                                  whi + oRM, wlo + oRM, blm, h1);
    head_dot_kernel<<<HD, 256>>>((const float4*)h1, Wm, bm, out + N_NODES);
    reset_kernel<<<SCAN_BLOCKS, 1024>>>();
}